// round 14
// baseline (speedup 1.0000x reference)
#include <cuda_runtime.h>
#include <cstdint>

#define HH 96
#define WW 96
#define HW 9216
#define CH 256
#define NB 2
#define NL 4
#define KK 2304   // CH*9

// ---------------------------------------------------------------------------
// Scratch (static device globals: no allocation at runtime)
// ---------------------------------------------------------------------------
__device__ float g_bufA[NB * CH * HW];          // ping
__device__ float g_bufB[NB * CH * HW];          // pong
__device__ float g_off [NB * 18 * HW];          // offsets per layer
__device__ float g_WTm [KK * 256];              // transposed main weights  [c*9+k][oc]
__device__ float g_WTo [KK * 32];               // transposed offset weights [c*9+k][oc(pad32)]

// ---------------------------------------------------------------------------
// Weight transpose: W[o][c*9+k]  ->  WT[c*9+k][o], zero-padded to OCP columns
// ---------------------------------------------------------------------------
__global__ void transpose_w_kernel(const float* __restrict__ win,
                                   float* __restrict__ wout,
                                   int O_in, int OCP)
{
    int t = blockIdx.x * blockDim.x + threadIdx.x;
    int total = KK * OCP;
    if (t >= total) return;
    int idx = t / OCP;
    int o   = t - idx * OCP;
    wout[t] = (o < O_in) ? win[o * KK + idx] : 0.0f;
}

// ---------------------------------------------------------------------------
// Unified deformable-conv GEMM.
//   Out[oc][pix] = sum_{c,k} WT[c*9+k][oc] * S[c][k][pix]  (+bias, optional relu)
//   S = bilinear samples at (y-1+k/3+oy, x-1+k%3+ox); HAS_OFF=false => regular
//   zero-padded 3x3 conv (validity mask == zero padding at integer coords).
// Block: OC_TILE x 64 pixels, 256 threads, thread tile MT x 4.
// ---------------------------------------------------------------------------
template <int OC_TILE, int MT, bool HAS_OFF, bool RELU>
__global__ __launch_bounds__(256, 2)
void deform_gemm_kernel(const float* __restrict__ xin,
                        const float* __restrict__ off,
                        const float* __restrict__ WT, int OC_PAD,
                        const float* __restrict__ bias,
                        float* __restrict__ out, int OC_OUT)
{
    constexpr int PX = 64;
    constexpr int NT = 4;
    constexpr int CC = 4;           // channels per K-chunk
    constexpr int THREADS = 256;
    constexpr int NPOS = HAS_OFF ? 9 * PX : 1;

    const int tid  = threadIdx.x;
    const int tx   = tid & 15;      // pixel group (0..15) -> 4 px each
    const int ty   = tid >> 4;      // oc group    (0..15) -> MT oc each
    const int b    = blockIdx.z;
    const int pix0 = blockIdx.x * PX;
    const int ocb  = blockIdx.y * OC_TILE;

    __shared__ float sS[CC][9][PX];
    __shared__ float sW[CC * 9][OC_TILE];
    __shared__ int   sIdx[NPOS][4];
    __shared__ float sWt [NPOS][4];

    // ---- per-block sampling geometry (channel-independent) ----
    if (HAS_OFF) {
        for (int it = tid; it < 9 * PX; it += THREADS) {
            int k   = it / PX;
            int p   = it - k * PX;
            int pix = pix0 + p;
            int y   = pix / WW;
            int x   = pix - y * WW;
            float oy = __ldg(off + (b * 18 + 2 * k    ) * HW + pix);
            float ox = __ldg(off + (b * 18 + 2 * k + 1) * HW + pix);
            float py  = (float)(y - 1 + k / 3) + oy;
            float pxf = (float)(x - 1 + k % 3) + ox;
            float y0f = floorf(py), x0f = floorf(pxf);
            float fy = py - y0f, fx = pxf - x0f;
            int y0 = (int)y0f, x0 = (int)x0f;
            float wy[2] = {1.0f - fy, fy};
            float wx[2] = {1.0f - fx, fx};
#pragma unroll
            for (int j = 0; j < 4; j++) {
                int yy = y0 + (j >> 1);
                int xx = x0 + (j & 1);
                bool v = (yy >= 0) && (yy < HH) && (xx >= 0) && (xx < WW);
                int yc = min(max(yy, 0), HH - 1);
                int xc = min(max(xx, 0), WW - 1);
                sIdx[it][j] = yc * WW + xc;
                sWt [it][j] = v ? (wy[j >> 1] * wx[j & 1]) : 0.0f;
            }
        }
        __syncthreads();
    }

    float acc[MT][NT];
#pragma unroll
    for (int i = 0; i < MT; i++)
#pragma unroll
        for (int j = 0; j < NT; j++) acc[i][j] = 0.0f;

    const float* xb = xin + (size_t)b * CH * HW;

    for (int c0 = 0; c0 < CH; c0 += CC) {
        __syncthreads();   // previous chunk's GEMM reads done before overwrite

        // ---- build sampled S for CC channels ----
        if (HAS_OFF) {
            for (int v = tid; v < CC * 9 * PX; v += THREADS) {
                int cc = v / (9 * PX);
                int it = v - cc * (9 * PX);
                const float* xc = xb + (c0 + cc) * HW;
                int4   id = *reinterpret_cast<const int4*  >(&sIdx[it][0]);
                float4 w  = *reinterpret_cast<const float4*>(&sWt [it][0]);
                float s = w.x * __ldg(xc + id.x) + w.y * __ldg(xc + id.y)
                        + w.z * __ldg(xc + id.z) + w.w * __ldg(xc + id.w);
                (&sS[0][0][0])[v] = s;
            }
        } else {
            for (int v = tid; v < CC * 9 * PX; v += THREADS) {
                int cc = v / (9 * PX);
                int it = v - cc * (9 * PX);
                int k  = it / PX;
                int p  = it - k * PX;
                int pix = pix0 + p;
                int y = pix / WW;
                int x = pix - y * WW;
                int yy = y + k / 3 - 1;
                int xx = x + (k % 3) - 1;
                float s = 0.0f;
                if (yy >= 0 && yy < HH && xx >= 0 && xx < WW)
                    s = __ldg(xb + (c0 + cc) * HW + yy * WW + xx);
                (&sS[0][0][0])[v] = s;
            }
        }

        // ---- stage transposed weights (coalesced float4) ----
        for (int v = tid; v < CC * 9 * OC_TILE / 4; v += THREADS) {
            int row  = v / (OC_TILE / 4);
            int col4 = v - row * (OC_TILE / 4);
            float4 wv = *reinterpret_cast<const float4*>(
                WT + (size_t)(c0 * 9 + row) * OC_PAD + ocb + col4 * 4);
            *(reinterpret_cast<float4*>(&sW[row][0]) + col4) = wv;
        }
        __syncthreads();

        // ---- FFMA micro-GEMM ----
#pragma unroll
        for (int cc = 0; cc < CC; cc++) {
#pragma unroll
            for (int k = 0; k < 9; k++) {
                float4 sv = *reinterpret_cast<const float4*>(&sS[cc][k][tx * NT]);
                float wv[MT];
                if constexpr (MT == 8) {
                    float4 wa = *reinterpret_cast<const float4*>(&sW[cc * 9 + k][ty * 8]);
                    float4 wb = *reinterpret_cast<const float4*>(&sW[cc * 9 + k][ty * 8 + 4]);
                    wv[0] = wa.x; wv[1] = wa.y; wv[2] = wa.z; wv[3] = wa.w;
                    wv[4] = wb.x; wv[5] = wb.y; wv[6] = wb.z; wv[7] = wb.w;
                } else {
                    float2 wa = *reinterpret_cast<const float2*>(&sW[cc * 9 + k][ty * 2]);
                    wv[0] = wa.x; wv[1] = wa.y;
                }
#pragma unroll
                for (int i = 0; i < MT; i++) {
                    acc[i][0] += wv[i] * sv.x;
                    acc[i][1] += wv[i] * sv.y;
                    acc[i][2] += wv[i] * sv.z;
                    acc[i][3] += wv[i] * sv.w;
                }
            }
        }
    }

    // ---- epilogue: bias (+relu), vectorized store ----
#pragma unroll
    for (int i = 0; i < MT; i++) {
        int oc = ocb + ty * MT + i;
        if (oc < OC_OUT) {
            float bv = __ldg(bias + oc);
            float4 r;
            r.x = acc[i][0] + bv;
            r.y = acc[i][1] + bv;
            r.z = acc[i][2] + bv;
            r.w = acc[i][3] + bv;
            if (RELU) {
                r.x = fmaxf(r.x, 0.0f);
                r.y = fmaxf(r.y, 0.0f);
                r.z = fmaxf(r.z, 0.0f);
                r.w = fmaxf(r.w, 0.0f);
            }
            *reinterpret_cast<float4*>(
                out + ((size_t)b * OC_OUT + oc) * HW + pix0 + tx * NT) = r;
        }
    }
}

// ---------------------------------------------------------------------------
// Launch: 4 layers, each = transpose weights, offset conv, deformable conv.
// All launches on the default stream (serialized); graph-capturable.
// ---------------------------------------------------------------------------
extern "C" void kernel_launch(void* const* d_in, const int* in_sizes, int n_in,
                              void* d_out, int out_size)
{
    (void)in_sizes; (void)n_in; (void)out_size;
    const float* x     = (const float*)d_in[0];
    const float* off_w = (const float*)d_in[1];
    const float* off_b = (const float*)d_in[2];
    const float* dw    = (const float*)d_in[3];
    const float* db    = (const float*)d_in[4];
    float* out = (float*)d_out;

    float *pA, *pB, *pOff, *pWTm, *pWTo;
    cudaGetSymbolAddress((void**)&pA,   g_bufA);
    cudaGetSymbolAddress((void**)&pB,   g_bufB);
    cudaGetSymbolAddress((void**)&pOff, g_off);
    cudaGetSymbolAddress((void**)&pWTm, g_WTm);
    cudaGetSymbolAddress((void**)&pWTo, g_WTo);

    for (int i = 0; i < NL; i++) {
        // transpose this layer's weights into [c*9+k][oc] layout
        transpose_w_kernel<<<(KK * 32  + 255) / 256, 256>>>(off_w + (size_t)i * 18 * KK, pWTo, 18, 32);
        transpose_w_kernel<<<(KK * 256 + 255) / 256, 256>>>(dw    + (size_t)i * CH * KK, pWTm, 256, 256);

        const float* in_i = (i == 0) ? x : ((i & 1) ? pA : pB);
        float* out_i = (i == 3) ? out : ((i & 1) ? pB : pA);

        // offset conv: 256->18 (padded to 32), zero offsets path, no relu
        dim3 g1(HW / 64, 1, NB);
        deform_gemm_kernel<32, 2, false, false><<<g1, 256>>>(
            in_i, nullptr, pWTo, 32, off_b + (size_t)i * 18, pOff, 18);

        // deformable conv: 256->256, bilinear path, bias + relu
        dim3 g2(HW / 64, 2, NB);
        deform_gemm_kernel<128, 8, true, true><<<g2, 256>>>(
            in_i, pOff, pWTm, 256, db + (size_t)i * CH, out_i, 256);
    }
}

// round 15
// speedup vs baseline: 1.0018x; 1.0018x over previous
#include <cuda_runtime.h>
#include <cstdint>

#define HH 96
#define WW 96
#define HW 9216
#define CH 256
#define NB 2
#define NL 4
#define KK 2304   // CH*9

// ---------------------------------------------------------------------------
// Scratch (static device globals: no allocation at runtime)
// ---------------------------------------------------------------------------
__device__ float g_bufA[NB * CH * HW];          // ping
__device__ float g_bufB[NB * CH * HW];          // pong
__device__ float g_off [NB * 18 * HW];          // offsets per layer
__device__ float g_WTm [KK * 256];              // transposed main weights  [c*9+k][oc]
__device__ float g_WTo [KK * 32];               // transposed offset weights [c*9+k][oc(pad32)]

// ---------------------------------------------------------------------------
// Weight transpose: W[o][c*9+k]  ->  WT[c*9+k][o], zero-padded to OCP columns
// ---------------------------------------------------------------------------
__global__ void transpose_w_kernel(const float* __restrict__ win,
                                   float* __restrict__ wout,
                                   int O_in, int OCP)
{
    int t = blockIdx.x * blockDim.x + threadIdx.x;
    int total = KK * OCP;
    if (t >= total) return;
    int idx = t / OCP;
    int o   = t - idx * OCP;
    wout[t] = (o < O_in) ? win[o * KK + idx] : 0.0f;
}

// ---------------------------------------------------------------------------
// Unified deformable-conv GEMM.
//   Out[oc][pix] = sum_{c,k} WT[c*9+k][oc] * S[c][k][pix]  (+bias, optional relu)
//   S = bilinear samples at (y-1+k/3+oy, x-1+k%3+ox); HAS_OFF=false => regular
//   zero-padded 3x3 conv (validity mask == zero padding at integer coords).
// Block: OC_TILE x 64 pixels, 256 threads, thread tile MT x 4.
// ---------------------------------------------------------------------------
template <int OC_TILE, int MT, bool HAS_OFF, bool RELU>
__global__ __launch_bounds__(256, 2)
void deform_gemm_kernel(const float* __restrict__ xin,
                        const float* __restrict__ off,
                        const float* __restrict__ WT, int OC_PAD,
                        const float* __restrict__ bias,
                        float* __restrict__ out, int OC_OUT)
{
    constexpr int PX = 64;
    constexpr int NT = 4;
    constexpr int CC = 4;           // channels per K-chunk
    constexpr int THREADS = 256;
    constexpr int NPOS = HAS_OFF ? 9 * PX : 1;

    const int tid  = threadIdx.x;
    const int tx   = tid & 15;      // pixel group (0..15) -> 4 px each
    const int ty   = tid >> 4;      // oc group    (0..15) -> MT oc each
    const int b    = blockIdx.z;
    const int pix0 = blockIdx.x * PX;
    const int ocb  = blockIdx.y * OC_TILE;

    __shared__ float sS[CC][9][PX];
    __shared__ float sW[CC * 9][OC_TILE];
    __shared__ int   sIdx[NPOS][4];
    __shared__ float sWt [NPOS][4];

    // ---- per-block sampling geometry (channel-independent) ----
    if (HAS_OFF) {
        for (int it = tid; it < 9 * PX; it += THREADS) {
            int k   = it / PX;
            int p   = it - k * PX;
            int pix = pix0 + p;
            int y   = pix / WW;
            int x   = pix - y * WW;
            float oy = __ldg(off + (b * 18 + 2 * k    ) * HW + pix);
            float ox = __ldg(off + (b * 18 + 2 * k + 1) * HW + pix);
            float py  = (float)(y - 1 + k / 3) + oy;
            float pxf = (float)(x - 1 + k % 3) + ox;
            float y0f = floorf(py), x0f = floorf(pxf);
            float fy = py - y0f, fx = pxf - x0f;
            int y0 = (int)y0f, x0 = (int)x0f;
            float wy[2] = {1.0f - fy, fy};
            float wx[2] = {1.0f - fx, fx};
#pragma unroll
            for (int j = 0; j < 4; j++) {
                int yy = y0 + (j >> 1);
                int xx = x0 + (j & 1);
                bool v = (yy >= 0) && (yy < HH) && (xx >= 0) && (xx < WW);
                int yc = min(max(yy, 0), HH - 1);
                int xc = min(max(xx, 0), WW - 1);
                sIdx[it][j] = yc * WW + xc;
                sWt [it][j] = v ? (wy[j >> 1] * wx[j & 1]) : 0.0f;
            }
        }
        __syncthreads();
    }

    float acc[MT][NT];
#pragma unroll
    for (int i = 0; i < MT; i++)
#pragma unroll
        for (int j = 0; j < NT; j++) acc[i][j] = 0.0f;

    const float* xb = xin + (size_t)b * CH * HW;

    for (int c0 = 0; c0 < CH; c0 += CC) {
        __syncthreads();   // previous chunk's GEMM reads done before overwrite

        // ---- build sampled S for CC channels ----
        if (HAS_OFF) {
            for (int v = tid; v < CC * 9 * PX; v += THREADS) {
                int cc = v / (9 * PX);
                int it = v - cc * (9 * PX);
                const float* xc = xb + (c0 + cc) * HW;
                int4   id = *reinterpret_cast<const int4*  >(&sIdx[it][0]);
                float4 w  = *reinterpret_cast<const float4*>(&sWt [it][0]);
                float s = w.x * __ldg(xc + id.x) + w.y * __ldg(xc + id.y)
                        + w.z * __ldg(xc + id.z) + w.w * __ldg(xc + id.w);
                (&sS[0][0][0])[v] = s;
            }
        } else {
            for (int v = tid; v < CC * 9 * PX; v += THREADS) {
                int cc = v / (9 * PX);
                int it = v - cc * (9 * PX);
                int k  = it / PX;
                int p  = it - k * PX;
                int pix = pix0 + p;
                int y = pix / WW;
                int x = pix - y * WW;
                int yy = y + k / 3 - 1;
                int xx = x + (k % 3) - 1;
                float s = 0.0f;
                if (yy >= 0 && yy < HH && xx >= 0 && xx < WW)
                    s = __ldg(xb + (c0 + cc) * HW + yy * WW + xx);
                (&sS[0][0][0])[v] = s;
            }
        }

        // ---- stage transposed weights (coalesced float4) ----
        for (int v = tid; v < CC * 9 * OC_TILE / 4; v += THREADS) {
            int row  = v / (OC_TILE / 4);
            int col4 = v - row * (OC_TILE / 4);
            float4 wv = *reinterpret_cast<const float4*>(
                WT + (size_t)(c0 * 9 + row) * OC_PAD + ocb + col4 * 4);
            *(reinterpret_cast<float4*>(&sW[row][0]) + col4) = wv;
        }
        __syncthreads();

        // ---- FFMA micro-GEMM ----
#pragma unroll
        for (int cc = 0; cc < CC; cc++) {
#pragma unroll
            for (int k = 0; k < 9; k++) {
                float4 sv = *reinterpret_cast<const float4*>(&sS[cc][k][tx * NT]);
                float wv[MT];
                if constexpr (MT == 8) {
                    float4 wa = *reinterpret_cast<const float4*>(&sW[cc * 9 + k][ty * 8]);
                    float4 wb = *reinterpret_cast<const float4*>(&sW[cc * 9 + k][ty * 8 + 4]);
                    wv[0] = wa.x; wv[1] = wa.y; wv[2] = wa.z; wv[3] = wa.w;
                    wv[4] = wb.x; wv[5] = wb.y; wv[6] = wb.z; wv[7] = wb.w;
                } else {
                    float2 wa = *reinterpret_cast<const float2*>(&sW[cc * 9 + k][ty * 2]);
                    wv[0] = wa.x; wv[1] = wa.y;
                }
#pragma unroll
                for (int i = 0; i < MT; i++) {
                    acc[i][0] += wv[i] * sv.x;
                    acc[i][1] += wv[i] * sv.y;
                    acc[i][2] += wv[i] * sv.z;
                    acc[i][3] += wv[i] * sv.w;
                }
            }
        }
    }

    // ---- epilogue: bias (+relu), vectorized store ----
#pragma unroll
    for (int i = 0; i < MT; i++) {
        int oc = ocb + ty * MT + i;
        if (oc < OC_OUT) {
            float bv = __ldg(bias + oc);
            float4 r;
            r.x = acc[i][0] + bv;
            r.y = acc[i][1] + bv;
            r.z = acc[i][2] + bv;
            r.w = acc[i][3] + bv;
            if (RELU) {
                r.x = fmaxf(r.x, 0.0f);
                r.y = fmaxf(r.y, 0.0f);
                r.z = fmaxf(r.z, 0.0f);
                r.w = fmaxf(r.w, 0.0f);
            }
            *reinterpret_cast<float4*>(
                out + ((size_t)b * OC_OUT + oc) * HW + pix0 + tx * NT) = r;
        }
    }
}

// ---------------------------------------------------------------------------
// Launch: 4 layers, each = transpose weights, offset conv, deformable conv.
// All launches on the default stream (serialized); graph-capturable.
// ---------------------------------------------------------------------------
extern "C" void kernel_launch(void* const* d_in, const int* in_sizes, int n_in,
                              void* d_out, int out_size)
{
    (void)in_sizes; (void)n_in; (void)out_size;
    const float* x     = (const float*)d_in[0];
    const float* off_w = (const float*)d_in[1];
    const float* off_b = (const float*)d_in[2];
    const float* dw    = (const float*)d_in[3];
    const float* db    = (const float*)d_in[4];
    float* out = (float*)d_out;

    float *pA, *pB, *pOff, *pWTm, *pWTo;
    cudaGetSymbolAddress((void**)&pA,   g_bufA);
    cudaGetSymbolAddress((void**)&pB,   g_bufB);
    cudaGetSymbolAddress((void**)&pOff, g_off);
    cudaGetSymbolAddress((void**)&pWTm, g_WTm);
    cudaGetSymbolAddress((void**)&pWTo, g_WTo);

    for (int i = 0; i < NL; i++) {
        // transpose this layer's weights into [c*9+k][oc] layout
        transpose_w_kernel<<<(KK * 32  + 255) / 256, 256>>>(off_w + (size_t)i * 18 * KK, pWTo, 18, 32);
        transpose_w_kernel<<<(KK * 256 + 255) / 256, 256>>>(dw    + (size_t)i * CH * KK, pWTm, 256, 256);

        const float* in_i = (i == 0) ? x : ((i & 1) ? pA : pB);
        float* out_i = (i == 3) ? out : ((i & 1) ? pB : pA);

        // offset conv: 256->18 (padded to 32), zero offsets path, no relu
        dim3 g1(HW / 64, 1, NB);
        deform_gemm_kernel<32, 2, false, false><<<g1, 256>>>(
            in_i, nullptr, pWTo, 32, off_b + (size_t)i * 18, pOff, 18);

        // deformable conv: 256->256, bilinear path, bias + relu
        dim3 g2(HW / 64, 2, NB);
        deform_gemm_kernel<128, 8, true, true><<<g2, 256>>>(
            in_i, pOff, pWTm, 256, db + (size_t)i * CH, out_i, 256);
    }
}